// round 1
// baseline (speedup 1.0000x reference)
#include <cuda_runtime.h>
#include <math.h>
#include <float.h>

#define TOKENS 8192
#define DIM 4096
#define NEXP 256
#define TOPK 8
#define NGROUPS 8
#define TOPKG 4
#define ROUTE_SCALE 2.5f

// Scratch for logits [TOKENS, NEXP] (8 MB) — static device array (no allocs allowed).
__device__ float g_logits[TOKENS * NEXP];

// ---------------- GEMM: C[T,E] = x[T,D] @ W[E,D]^T (fp32, packed f32x2 FMA) ----------------
#define BM 128
#define BN 128
#define BK 16
#define LDS_A 132   // BM + 4 pad (keeps float4 reads 16B-aligned)
#define LDS_B 132

__device__ __forceinline__ void fma2(float2& d, float2 a, float2 b) {
    unsigned long long aa, bb;
    aa = *reinterpret_cast<unsigned long long*>(&a);
    bb = *reinterpret_cast<unsigned long long*>(&b);
    unsigned long long& dd = *reinterpret_cast<unsigned long long*>(&d);
    asm("fma.rn.f32x2 %0, %1, %2, %0;" : "+l"(dd) : "l"(aa), "l"(bb));
}

__global__ __launch_bounds__(256, 1)
void gate_gemm_kernel(const float* __restrict__ x, const float* __restrict__ W) {
    __shared__ float As[BK * LDS_A];
    __shared__ float Bs[BK * LDS_B];

    const int tid = threadIdx.x;
    const int tx = tid & 15;        // 0..15 -> expert sub-tile
    const int ty = tid >> 4;        // 0..15 -> token sub-tile
    const int rowBase = blockIdx.y * BM;   // token base
    const int colBase = blockIdx.x * BN;   // expert base

    float2 acc[8][4];
#pragma unroll
    for (int m = 0; m < 8; m++)
#pragma unroll
        for (int n = 0; n < 4; n++) acc[m][n] = make_float2(0.f, 0.f);

    for (int k0 = 0; k0 < DIM; k0 += BK) {
        // Load A tile (128 rows x 16 k) and B tile, transposed into smem [k][row]
#pragma unroll
        for (int i = 0; i < 2; i++) {
            int id = tid + i * 256;
            int r = id >> 2;
            int c4 = (id & 3) << 2;
            float4 va = *reinterpret_cast<const float4*>(&x[(size_t)(rowBase + r) * DIM + k0 + c4]);
            As[(c4 + 0) * LDS_A + r] = va.x;
            As[(c4 + 1) * LDS_A + r] = va.y;
            As[(c4 + 2) * LDS_A + r] = va.z;
            As[(c4 + 3) * LDS_A + r] = va.w;
            float4 vb = *reinterpret_cast<const float4*>(&W[(size_t)(colBase + r) * DIM + k0 + c4]);
            Bs[(c4 + 0) * LDS_B + r] = vb.x;
            Bs[(c4 + 1) * LDS_B + r] = vb.y;
            Bs[(c4 + 2) * LDS_B + r] = vb.z;
            Bs[(c4 + 3) * LDS_B + r] = vb.w;
        }
        __syncthreads();

#pragma unroll
        for (int k = 0; k < BK; k++) {
            float4 a0 = *reinterpret_cast<const float4*>(&As[k * LDS_A + ty * 8]);
            float4 a1 = *reinterpret_cast<const float4*>(&As[k * LDS_A + ty * 8 + 4]);
            float4 b0 = *reinterpret_cast<const float4*>(&Bs[k * LDS_B + tx * 8]);
            float4 b1 = *reinterpret_cast<const float4*>(&Bs[k * LDS_B + tx * 8 + 4]);
            float av[8] = {a0.x, a0.y, a0.z, a0.w, a1.x, a1.y, a1.z, a1.w};
            float2 bv[4] = {make_float2(b0.x, b0.y), make_float2(b0.z, b0.w),
                            make_float2(b1.x, b1.y), make_float2(b1.z, b1.w)};
#pragma unroll
            for (int m = 0; m < 8; m++) {
                float2 am = make_float2(av[m], av[m]);
#pragma unroll
                for (int n = 0; n < 4; n++) fma2(acc[m][n], am, bv[n]);
            }
        }
        __syncthreads();
    }

    // Epilogue: write logits
#pragma unroll
    for (int m = 0; m < 8; m++) {
        int row = rowBase + ty * 8 + m;
        float2* dst = reinterpret_cast<float2*>(&g_logits[(size_t)row * NEXP + colBase + tx * 8]);
#pragma unroll
        for (int n = 0; n < 4; n++) dst[n] = acc[m][n];
    }
}

// ---------------- Routing: one warp per token ----------------
// Lane l owns experts [l*8, l*8+8). Group g = experts [g*32,(g+1)*32) = lanes 4g..4g+3.
__global__ __launch_bounds__(256)
void gate_route_kernel(const float* __restrict__ bias, float* __restrict__ out) {
    const int token = (blockIdx.x * blockDim.x + threadIdx.x) >> 5;
    const int lane = threadIdx.x & 31;
    if (token >= TOKENS) return;

    const float* lg = g_logits + (size_t)token * NEXP;
    const int ebase = lane * 8;

    float4 l0 = *reinterpret_cast<const float4*>(&lg[ebase]);
    float4 l1 = *reinterpret_cast<const float4*>(&lg[ebase + 4]);
    float4 bb0 = *reinterpret_cast<const float4*>(&bias[ebase]);
    float4 bb1 = *reinterpret_cast<const float4*>(&bias[ebase + 4]);

    float s[8], sb[8];
    {
        float lv[8] = {l0.x, l0.y, l0.z, l0.w, l1.x, l1.y, l1.z, l1.w};
        float bv[8] = {bb0.x, bb0.y, bb0.z, bb0.w, bb1.x, bb1.y, bb1.z, bb1.w};
#pragma unroll
        for (int j = 0; j < 8; j++) {
            s[j] = 1.0f / (1.0f + expf(-lv[j]));
            sb[j] = s[j] + bv[j];
        }
    }

    // local top-2 of this lane's 8 biased scores
    float t1 = -FLT_MAX, t2 = -FLT_MAX;
#pragma unroll
    for (int j = 0; j < 8; j++) {
        if (sb[j] > t1) { t2 = t1; t1 = sb[j]; }
        else if (sb[j] > t2) { t2 = sb[j]; }
    }
    // merge top-2 across the 4 lanes of the group
#pragma unroll
    for (int off = 1; off < 4; off <<= 1) {
        float o1 = __shfl_xor_sync(0xffffffffu, t1, off);
        float o2 = __shfl_xor_sync(0xffffffffu, t2, off);
        float n1 = fmaxf(t1, o1);
        float n2 = fmaxf(fminf(t1, o1), fmaxf(t2, o2));
        t1 = n1; t2 = n2;
    }
    float gscore = t1 + t2;
    int myg = lane >> 2;

    // rank of my group among the 8 group scores (ties -> lower group index wins)
    int rank = 0;
#pragma unroll
    for (int j = 0; j < 8; j++) {
        float gj = __shfl_sync(0xffffffffu, gscore, j * 4);
        rank += (gj > gscore) || (gj == gscore && j < myg);
    }
    bool gsel = rank < TOPKG;

    // masked candidate scores: exact jax semantics (sg * mask) -> masked entries are 0.0
    float v[8];
#pragma unroll
    for (int j = 0; j < 8; j++) v[j] = gsel ? sb[j] : 0.0f;

    int sel_idx = 0;
    float sel_s = 0.0f;
    float ssum = 0.0f;

#pragma unroll
    for (int r = 0; r < TOPK; r++) {
        // local argmax (strict > -> lowest index wins ties)
        float bv = -FLT_MAX, bs = 0.0f;
        int bidx = ebase;
#pragma unroll
        for (int j = 0; j < 8; j++) {
            if (v[j] > bv) { bv = v[j]; bidx = ebase + j; bs = s[j]; }
        }
        // warp argmax: higher value wins; on ties, lower expert index wins
#pragma unroll
        for (int off = 16; off > 0; off >>= 1) {
            float ov = __shfl_xor_sync(0xffffffffu, bv, off);
            int oi = __shfl_xor_sync(0xffffffffu, bidx, off);
            float os = __shfl_xor_sync(0xffffffffu, bs, off);
            if (ov > bv || (ov == bv && oi < bidx)) { bv = ov; bidx = oi; bs = os; }
        }
        if (lane == r) { sel_idx = bidx; sel_s = bs; }
        ssum += bs;
        // exclude winner
        if (lane == (bidx >> 3)) {
            int slot = bidx & 7;
#pragma unroll
            for (int j = 0; j < 8; j++)
                if (j == slot) v[j] = -FLT_MAX;
        }
    }

    if (lane < TOPK) {
        float w = sel_s / ssum * ROUTE_SCALE;
        out[(size_t)token * TOPK + lane] = w;
        out[(size_t)TOKENS * TOPK + (size_t)token * TOPK + lane] = (float)sel_idx;
    }
}

extern "C" void kernel_launch(void* const* d_in, const int* in_sizes, int n_in,
                              void* d_out, int out_size) {
    const float* x = (const float*)d_in[0];
    const float* W = (const float*)d_in[1];
    const float* bias = (const float*)d_in[2];
    float* out = (float*)d_out;

    dim3 grid(NEXP / BN, TOKENS / BM);
    gate_gemm_kernel<<<grid, 256>>>(x, W);

    // one warp per token, 8 warps per block
    gate_route_kernel<<<TOKENS / 8, 256>>>(bias, out);
}

// round 4
// speedup vs baseline: 1.8645x; 1.8645x over previous
#include <cuda_runtime.h>
#include <math.h>
#include <float.h>
#include <stdint.h>

#define TOKENS 8192
#define DIM 4096
#define NEXP 256
#define TOPK 8
#define TOPKG 4
#define ROUTE_SCALE 2.5f

// Logits scratch [TOKENS, NEXP] (8 MB)
__device__ float g_logits[TOKENS * NEXP];

// ===================== GEMM: bf16x3 split (6 terms) via mma.sync m16n8k16 =====================
// CTA tile 128(tokens) x 128(experts), K chunk 32, 2-stage smem, register-prefetch LDG.
// smem per stage: 6 bf16 tiles [128 rows x 32 k], row stride 80B (conflict-free ldmatrix).

#define BKF 32
#define STRB 80                      // bytes per bf16 tile row (32 bf16 = 64B data + pad)
#define TILE_B (128 * STRB)          // 10240
#define STAGE_B (6 * TILE_B)         // 61440
#define NCHUNK (DIM / BKF)           // 128
#define SMEM_TOTAL (2 * STAGE_B)     // 122880

__device__ __forceinline__ uint32_t smem_u32(const void* p) {
    uint32_t a;
    asm("{ .reg .u64 t; cvta.to.shared.u64 t, %1; cvt.u32.u64 %0, t; }" : "=r"(a) : "l"(p));
    return a;
}
__device__ __forceinline__ uint32_t packbf(float hi, float lo) {
    uint32_t r;
    asm("cvt.rn.bf16x2.f32 %0, %1, %2;" : "=r"(r) : "f"(hi), "f"(lo));
    return r;
}
__device__ __forceinline__ float unlo(uint32_t p) { return __uint_as_float(p << 16); }
__device__ __forceinline__ float unhi(uint32_t p) { return __uint_as_float(p & 0xffff0000u); }

__device__ __forceinline__ void ldm_x4(uint32_t* r, uint32_t a) {
    asm volatile("ldmatrix.sync.aligned.m8n8.x4.shared.b16 {%0,%1,%2,%3}, [%4];"
        : "=r"(r[0]), "=r"(r[1]), "=r"(r[2]), "=r"(r[3]) : "r"(a));
}
__device__ __forceinline__ void ldm_x2(uint32_t* r, uint32_t a) {
    asm volatile("ldmatrix.sync.aligned.m8n8.x2.shared.b16 {%0,%1}, [%2];"
        : "=r"(r[0]), "=r"(r[1]) : "r"(a));
}
__device__ __forceinline__ void mma_bf16(float* c, const uint32_t* a, const uint32_t* b) {
    asm volatile(
        "mma.sync.aligned.m16n8k16.row.col.f32.bf16.bf16.f32 "
        "{%0,%1,%2,%3}, {%4,%5,%6,%7}, {%8,%9}, {%0,%1,%2,%3};"
        : "+f"(c[0]), "+f"(c[1]), "+f"(c[2]), "+f"(c[3])
        : "r"(a[0]), "r"(a[1]), "r"(a[2]), "r"(a[3]), "r"(b[0]), "r"(b[1]));
}
#define STS64(a, r0, r1) \
    asm volatile("st.shared.v2.b32 [%0], {%1, %2};" :: "r"(a), "r"(r0), "r"(r1) : "memory")

__global__ __launch_bounds__(256, 1)
void gate_gemm_bf16x3(const float* __restrict__ x, const float* __restrict__ W) {
    extern __shared__ char smem[];
    const uint32_t sb = smem_u32(smem);

    const int tid = threadIdx.x;
    const int wid = tid >> 5;
    const int lane = tid & 31;
    const int q = lane >> 2;
    const int t4 = lane & 3;
    const int wm = wid & 1;          // m offset: 0/64
    const int wn = wid >> 1;         // n offset: 0..3 * 32
    const int rowBase = blockIdx.y * 128;
    const int colBase = blockIdx.x * 128;

    // ---- producer indexing: warps 0-3 load A(x) rows, warps 4-7 load B(W) rows ----
    const int ptile = wid >> 2;                       // 0 = A, 1 = B
    const int prow = (wid & 3) * 32 + (lane >> 3);    // + it*4, covers 32 rows/warp
    const int pseg = lane & 7;                        // 16B segment in the 128B k-row
    const float* gsrc = (ptile == 0)
        ? &x[(size_t)(rowBase + prow) * DIM + pseg * 4]
        : &W[(size_t)(colBase + prow) * DIM + pseg * 4];
    const uint32_t pStageOff = (uint32_t)(ptile * 3 * TILE_B + prow * STRB + pseg * 8);

    // ---- consumer ldmatrix lane address components ----
    const uint32_t aBase = (uint32_t)((wm * 64 + ((lane >> 3) & 1) * 8 + (lane & 7)) * STRB
                                      + (lane >> 4) * 16);
    const uint32_t bBase = (uint32_t)(3 * TILE_B + (wn * 32 + (lane & 7)) * STRB
                                      + ((lane >> 3) & 1) * 16);

    float accM[4][4][4];   // hh
    float accS[4][4][4];   // hm + mh + mm + hl + lh
#pragma unroll
    for (int mt = 0; mt < 4; mt++)
#pragma unroll
        for (int nt = 0; nt < 4; nt++)
#pragma unroll
            for (int e = 0; e < 4; e++) { accM[mt][nt][e] = 0.f; accS[mt][nt][e] = 0.f; }

    float4 pf[8];

    // split + STS one stage from prefetch registers
    auto produce = [&](int s) {
        const uint32_t base = sb + (uint32_t)s * STAGE_B + pStageOff;
#pragma unroll
        for (int it = 0; it < 8; it++) {
            const float4 v = pf[it];
            // pair (x,y)
            uint32_t hp0 = packbf(v.y, v.x);
            float r0 = v.x - unlo(hp0), r1 = v.y - unhi(hp0);
            uint32_t mp0 = packbf(r1, r0);
            float l0 = r0 - unlo(mp0), l1 = r1 - unhi(mp0);
            uint32_t lp0 = packbf(l1, l0);
            // pair (z,w)
            uint32_t hp1 = packbf(v.w, v.z);
            float r2 = v.z - unlo(hp1), r3 = v.w - unhi(hp1);
            uint32_t mp1 = packbf(r3, r2);
            float l2 = r2 - unlo(mp1), l3 = r3 - unhi(mp1);
            uint32_t lp1 = packbf(l3, l2);

            const uint32_t a = base + (uint32_t)(it * 4 * STRB);
            STS64(a, hp0, hp1);
            STS64(a + TILE_B, mp0, mp1);
            STS64(a + 2 * TILE_B, lp0, lp1);
        }
    };

    // prologue: chunk 0
#pragma unroll
    for (int it = 0; it < 8; it++)
        pf[it] = *reinterpret_cast<const float4*>(gsrc + (size_t)it * 4 * DIM);
    produce(0);
    __syncthreads();

    for (int g = 0; g < NCHUNK; g++) {
        if (g + 1 < NCHUNK) {
            const float* src = gsrc + (size_t)(g + 1) * BKF;
#pragma unroll
            for (int it = 0; it < 8; it++)
                pf[it] = *reinterpret_cast<const float4*>(src + (size_t)it * 4 * DIM);
        }

        const uint32_t stg = sb + (uint32_t)(g & 1) * STAGE_B;
#pragma unroll
        for (int ks = 0; ks < 2; ks++) {
            const uint32_t kb2 = (uint32_t)(ks * 32);   // k-step byte offset (16 bf16)
            uint32_t Ah[4][4], Am[4][4], Al[4][4];
#pragma unroll
            for (int mt = 0; mt < 4; mt++) {
                const uint32_t a = stg + aBase + (uint32_t)(mt * 16 * STRB) + kb2;
                ldm_x4(Ah[mt], a);
                ldm_x4(Am[mt], a + TILE_B);
                ldm_x4(Al[mt], a + 2 * TILE_B);
            }
#pragma unroll
            for (int nt = 0; nt < 4; nt++) {
                const uint32_t b = stg + bBase + (uint32_t)(nt * 8 * STRB) + kb2;
                uint32_t Bh[2], Bm[2], Bl[2];
                ldm_x2(Bh, b);
                ldm_x2(Bm, b + TILE_B);
                ldm_x2(Bl, b + 2 * TILE_B);
#pragma unroll
                for (int mt = 0; mt < 4; mt++) {
                    mma_bf16(accM[mt][nt], Ah[mt], Bh);   // hh (main chain)
                    mma_bf16(accS[mt][nt], Ah[mt], Bm);   // hm
                    mma_bf16(accS[mt][nt], Am[mt], Bh);   // mh
                    mma_bf16(accS[mt][nt], Am[mt], Bm);   // mm
                    mma_bf16(accS[mt][nt], Ah[mt], Bl);   // hl
                    mma_bf16(accS[mt][nt], Al[mt], Bh);   // lh
                }
            }
        }

        if (g + 1 < NCHUNK) produce((g + 1) & 1);
        __syncthreads();
    }

    // ---- epilogue ----
#pragma unroll
    for (int mt = 0; mt < 4; mt++) {
        const int row0 = rowBase + wm * 64 + mt * 16 + q;
#pragma unroll
        for (int nt = 0; nt < 4; nt++) {
            const int col = colBase + wn * 32 + nt * 8 + t4 * 2;
            float c0 = accM[mt][nt][0] + accS[mt][nt][0];
            float c1 = accM[mt][nt][1] + accS[mt][nt][1];
            float c2 = accM[mt][nt][2] + accS[mt][nt][2];
            float c3 = accM[mt][nt][3] + accS[mt][nt][3];
            *reinterpret_cast<float2*>(&g_logits[(size_t)row0 * NEXP + col]) = make_float2(c0, c1);
            *reinterpret_cast<float2*>(&g_logits[(size_t)(row0 + 8) * NEXP + col]) = make_float2(c2, c3);
        }
    }
}

// ===================== Routing: one warp per token =====================
__global__ __launch_bounds__(256)
void gate_route_kernel(const float* __restrict__ bias, float* __restrict__ out) {
    const int token = (blockIdx.x * blockDim.x + threadIdx.x) >> 5;
    const int lane = threadIdx.x & 31;
    if (token >= TOKENS) return;

    const float* lg = g_logits + (size_t)token * NEXP;
    const int ebase = lane * 8;

    float4 l0 = *reinterpret_cast<const float4*>(&lg[ebase]);
    float4 l1 = *reinterpret_cast<const float4*>(&lg[ebase + 4]);
    float4 bb0 = *reinterpret_cast<const float4*>(&bias[ebase]);
    float4 bb1 = *reinterpret_cast<const float4*>(&bias[ebase + 4]);

    float s[8], sb[8];
    {
        float lv[8] = {l0.x, l0.y, l0.z, l0.w, l1.x, l1.y, l1.z, l1.w};
        float bv[8] = {bb0.x, bb0.y, bb0.z, bb0.w, bb1.x, bb1.y, bb1.z, bb1.w};
#pragma unroll
        for (int j = 0; j < 8; j++) {
            s[j] = 1.0f / (1.0f + expf(-lv[j]));
            sb[j] = s[j] + bv[j];
        }
    }

    float t1 = -FLT_MAX, t2 = -FLT_MAX;
#pragma unroll
    for (int j = 0; j < 8; j++) {
        if (sb[j] > t1) { t2 = t1; t1 = sb[j]; }
        else if (sb[j] > t2) { t2 = sb[j]; }
    }
#pragma unroll
    for (int off = 1; off < 4; off <<= 1) {
        float o1 = __shfl_xor_sync(0xffffffffu, t1, off);
        float o2 = __shfl_xor_sync(0xffffffffu, t2, off);
        float n1 = fmaxf(t1, o1);
        float n2 = fmaxf(fminf(t1, o1), fmaxf(t2, o2));
        t1 = n1; t2 = n2;
    }
    float gscore = t1 + t2;
    int myg = lane >> 2;

    int rank = 0;
#pragma unroll
    for (int j = 0; j < 8; j++) {
        float gj = __shfl_sync(0xffffffffu, gscore, j * 4);
        rank += (gj > gscore) || (gj == gscore && j < myg);
    }
    bool gsel = rank < TOPKG;

    float v[8];
#pragma unroll
    for (int j = 0; j < 8; j++) v[j] = gsel ? sb[j] : 0.0f;

    int sel_idx = 0;
    float sel_s = 0.0f;
    float ssum = 0.0f;

#pragma unroll
    for (int r = 0; r < TOPK; r++) {
        float bv = -FLT_MAX, bs = 0.0f;
        int bidx = ebase;
#pragma unroll
        for (int j = 0; j < 8; j++) {
            if (v[j] > bv) { bv = v[j]; bidx = ebase + j; bs = s[j]; }
        }
#pragma unroll
        for (int off = 16; off > 0; off >>= 1) {
            float ov = __shfl_xor_sync(0xffffffffu, bv, off);
            int oi = __shfl_xor_sync(0xffffffffu, bidx, off);
            float os = __shfl_xor_sync(0xffffffffu, bs, off);
            if (ov > bv || (ov == bv && oi < bidx)) { bv = ov; bidx = oi; bs = os; }
        }
        if (lane == r) { sel_idx = bidx; sel_s = bs; }
        ssum += bs;
        if (lane == (bidx >> 3)) {
            int slot = bidx & 7;
#pragma unroll
            for (int j = 0; j < 8; j++)
                if (j == slot) v[j] = -FLT_MAX;
        }
    }

    if (lane < TOPK) {
        float w = sel_s / ssum * ROUTE_SCALE;
        out[(size_t)token * TOPK + lane] = w;
        out[(size_t)TOKENS * TOPK + (size_t)token * TOPK + lane] = (float)sel_idx;
    }
}

extern "C" void kernel_launch(void* const* d_in, const int* in_sizes, int n_in,
                              void* d_out, int out_size) {
    const float* x = (const float*)d_in[0];
    const float* W = (const float*)d_in[1];
    const float* bias = (const float*)d_in[2];
    float* out = (float*)d_out;

    cudaFuncSetAttribute(gate_gemm_bf16x3, cudaFuncAttributeMaxDynamicSharedMemorySize, SMEM_TOTAL);

    dim3 grid(NEXP / 128, TOKENS / 128);
    gate_gemm_bf16x3<<<grid, 256, SMEM_TOTAL>>>(x, W);

    gate_route_kernel<<<TOKENS / 8, 256>>>(bias, out);
}